// round 1
// baseline (speedup 1.0000x reference)
#include <cuda_runtime.h>
#include <math.h>

// Fixed problem shapes (from setup_inputs)
#define BB 8
#define CC 3
#define HF 1024
#define WF 2048
#define MM 32
#define HH 128
#define WW 256
#define HW (HH*WW)

// ---------------- scratch (device globals; no allocations allowed) ----------
__device__ float  g_depth[BB*HW];          // 1 MB
__device__ float  g_nlin [BB*3*HW];        // 3 MB  (normal, channel-major flatten per batch)
__device__ float4 g_imgp [BB*HW];          // 4 MB  pooled image, (b,y,x) -> {c0,c1,c2,pad}
__device__ float  g_Hm   [BB*MM*6];        // homography top-2 rows

// ---------------- kernel 1: 8x8 average pool -------------------------------
__global__ void pool_kernel(const float* __restrict__ img) {
    int idx = blockIdx.x * blockDim.x + threadIdx.x;
    if (idx >= BB*HW) return;
    int b = idx / HW, pix = idx % HW, y = pix / WW, x = pix % WW;
    float acc[3];
#pragma unroll
    for (int c = 0; c < 3; c++) {
        const float* base = img + (((size_t)(b*3 + c)*HF + (size_t)y*8)*WF) + (size_t)x*8;
        float s = 0.f;
#pragma unroll
        for (int r = 0; r < 8; r++) {
            const float4* p = (const float4*)(base + (size_t)r*WF);
            float4 a = p[0], q = p[1];
            s += a.x + a.y + a.z + a.w + q.x + q.y + q.z + q.w;
        }
        acc[c] = s * (1.f/64.f);
    }
    g_imgp[idx] = make_float4(acc[0], acc[1], acc[2], 0.f);
}

// ---------------- kernel 2: depth + normals --------------------------------
__global__ void depth_normal_kernel(const float* __restrict__ disp,
                                    const float* __restrict__ intrs,
                                    const float* __restrict__ baseline) {
    int idx = blockIdx.x * blockDim.x + threadIdx.x;
    if (idx >= BB*HW) return;
    int b = idx / HW, pix = idx % HW, y = pix / WW, x = pix % WW;
    float f  = 0.5f*(intrs[b*9 + 0] + intrs[b*9 + 4]);
    float sc = baseline[b] * f * (1.f/2048.f);
    const float* drow = disp + (size_t)b*HW;
    float dxp = (x < WW-1) ? sc/drow[pix+1]  : 0.f;
    float dxm = (x > 0)    ? sc/drow[pix-1]  : 0.f;
    float dyp = (y < HH-1) ? sc/drow[pix+WW] : 0.f;
    float dym = (y > 0)    ? sc/drow[pix-WW] : 0.f;
    float gx = 0.5f*(dxp - dxm);
    float gy = 0.5f*(dyp - dym);
    float inv = rsqrtf(gx*gx + gy*gy + 1.f);
    g_depth[idx] = sc/drow[pix];
    float* nb = g_nlin + (size_t)b*3*HW;
    nb[pix]          = -gx*inv;
    nb[HW   + pix]   = -gy*inv;
    nb[2*HW + pix]   =  inv;
}

// ---------------- kernel 3: per-plane softmax sums + homography ------------
__global__ void plane_kernel(const float* __restrict__ masks,
                             const float* __restrict__ intrs,
                             const float* __restrict__ baseline) {
    int bm = blockIdx.x;          // 0..BB*MM-1
    int b  = bm / MM;
    int tid = threadIdx.x;        // 256 threads
    const float* mrow = masks + (size_t)bm*HW;

    __shared__ float red[256];
    float mx = -1e30f;
    for (int i = tid; i < HW; i += 256) mx = fmaxf(mx, mrow[i]);
    red[tid] = mx; __syncthreads();
    for (int s = 128; s > 0; s >>= 1) {
        if (tid < s) red[tid] = fmaxf(red[tid], red[tid+s]);
        __syncthreads();
    }
    mx = red[0]; __syncthreads();

    float se=0.f, sd=0.f, s0=0.f, s1=0.f, s2=0.f;
    const float* dep = g_depth + (size_t)b*HW;
    const float* nl  = g_nlin  + (size_t)b*3*HW;
    for (int i = tid; i < HW; i += 256) {
        float e = __expf(mrow[i] - mx);
        se += e;
        sd += e * dep[i];
        int j = 3*i;                      // faithful .view(B, h*w, 3) memory reinterpret
        s0 += e * nl[j];
        s1 += e * nl[j+1];
        s2 += e * nl[j+2];
    }
    __shared__ float r5[5][256];
    r5[0][tid]=se; r5[1][tid]=sd; r5[2][tid]=s0; r5[3][tid]=s1; r5[4][tid]=s2;
    __syncthreads();
    for (int s = 128; s > 0; s >>= 1) {
        if (tid < s)
#pragma unroll
            for (int k = 0; k < 5; k++) r5[k][tid] += r5[k][tid+s];
        __syncthreads();
    }
    if (tid == 0) {
        float inv = 1.f / r5[0][0];
        float d  = r5[1][0]*inv;
        float n0 = r5[2][0]*inv, n1 = r5[3][0]*inv, n2 = r5[4][0]*inv;
        float f  = intrs[b*9+0], g = intrs[b*9+4];
        float cx = intrs[b*9+2], cy = intrs[b*9+5];
        float bl = baseline[b];
        float t0 = bl*n0/d, t1 = bl*n1/d, t2 = bl*n2/d;
        // Hm = K * (I + (bl/d) e3 n^T) * K^-1, top two rows
        float* o = g_Hm + bm*6;
        o[0] = 1.f + cx*t0/f;
        o[1] = cx*t1/g;
        o[2] = cx*t2 - cx*cx*t0/f - cx*cy*t1/g;
        o[3] = cy*t0/f;
        o[4] = 1.f + cy*t1/g;
        o[5] = cy*t2 - cx*cy*t0/f - cy*cy*t1/g;
    }
}

// ---------------- kernel 4: warp + blend -----------------------------------
__global__ void warp_blend_kernel(const float* __restrict__ masks,
                                  float* __restrict__ out) {
    int idx = blockIdx.x * blockDim.x + threadIdx.x;
    if (idx >= BB*HW) return;
    int b = idx / HW, pix = idx % HW, y = pix / WW, x = pix % WW;
    float gxx = -1.f + 2.f*(float)x/(float)(WW-1);
    float gyy = -1.f + 2.f*(float)y/(float)(HH-1);

    const float* mbase = masks + (size_t)b*MM*HW + pix;
    float ev[MM];
    float mx = -1e30f;
#pragma unroll
    for (int m = 0; m < MM; m++) { ev[m] = mbase[(size_t)m*HW]; mx = fmaxf(mx, ev[m]); }
    float se = 0.f;
#pragma unroll
    for (int m = 0; m < MM; m++) { ev[m] = __expf(ev[m] - mx); se += ev[m]; }
    float inv = 1.f/se;

    const float4* ip = g_imgp + (size_t)b*HW;
    float a0=0.f, a1=0.f, a2=0.f;
#pragma unroll
    for (int m = 0; m < MM; m++) {
        const float* Hp = g_Hm + (b*MM + m)*6;
        float u = Hp[0]*gxx + Hp[1]*gyy + Hp[2];
        float v = Hp[3]*gxx + Hp[4]*gyy + Hp[5];
        float ix = (u + 1.f)*0.5f*(float)(WW-1);
        float iy = (v + 1.f)*0.5f*(float)(HH-1);
        float x0f = floorf(ix), y0f = floorf(iy);
        float wx = ix - x0f,    wy = iy - y0f;
        int x0 = (int)x0f, y0 = (int)y0f;
        bool vx0 = (x0   >= 0) && (x0   <= WW-1);
        bool vx1 = (x0+1 >= 0) && (x0+1 <= WW-1);
        bool vy0 = (y0   >= 0) && (y0   <= HH-1);
        bool vy1 = (y0+1 >= 0) && (y0+1 <= HH-1);
        int xc0 = min(max(x0,   0), WW-1), xc1 = min(max(x0+1, 0), WW-1);
        int yc0 = min(max(y0,   0), HH-1), yc1 = min(max(y0+1, 0), HH-1);
        float4 z = make_float4(0.f,0.f,0.f,0.f);
        float4 c00 = (vx0 && vy0) ? ip[yc0*WW + xc0] : z;
        float4 c10 = (vx1 && vy0) ? ip[yc0*WW + xc1] : z;
        float4 c01 = (vx0 && vy1) ? ip[yc1*WW + xc0] : z;
        float4 c11 = (vx1 && vy1) ? ip[yc1*WW + xc1] : z;
        float w00 = (1.f-wx)*(1.f-wy), w10 = wx*(1.f-wy);
        float w01 = (1.f-wx)*wy,       w11 = wx*wy;
        float wm = ev[m]*inv;
        a0 += wm*(c00.x*w00 + c10.x*w10 + c01.x*w01 + c11.x*w11);
        a1 += wm*(c00.y*w00 + c10.y*w10 + c01.y*w01 + c11.y*w11);
        a2 += wm*(c00.z*w00 + c10.z*w10 + c01.z*w01 + c11.z*w11);
    }
    out[((size_t)b*3 + 0)*HW + pix] = a0;
    out[((size_t)b*3 + 1)*HW + pix] = a1;
    out[((size_t)b*3 + 2)*HW + pix] = a2;
}

// ---------------- launch -----------------------------------------------------
extern "C" void kernel_launch(void* const* d_in, const int* in_sizes, int n_in,
                              void* d_out, int out_size) {
    const float* img      = (const float*)d_in[0];
    const float* masks    = (const float*)d_in[1];
    const float* disp     = (const float*)d_in[2];
    const float* intrs    = (const float*)d_in[3];
    const float* baseline = (const float*)d_in[4];
    float* out = (float*)d_out;

    const int threads = 256;
    const int px_blocks = (BB*HW + threads - 1) / threads;

    pool_kernel<<<px_blocks, threads>>>(img);
    depth_normal_kernel<<<px_blocks, threads>>>(disp, intrs, baseline);
    plane_kernel<<<BB*MM, threads>>>(masks, intrs, baseline);
    warp_blend_kernel<<<px_blocks, threads>>>(masks, out);
}

// round 2
// speedup vs baseline: 1.0195x; 1.0195x over previous
#include <cuda_runtime.h>
#include <math.h>

// Fixed problem shapes (from setup_inputs)
#define BB 8
#define CC 3
#define HF 1024
#define WF 2048
#define MM 32
#define HH 128
#define WW 256
#define HW (HH*WW)

// ---------------- scratch (device globals; no allocations allowed) ----------
__device__ float  g_depth[BB*HW];          // 1 MB
__device__ float  g_nlin [BB*3*HW];        // 3 MB  (normal, channel-major flatten per batch)
__device__ float4 g_imgp [BB*HW];          // 4 MB  pooled image, (b,y,x) -> {c0,c1,c2,pad}
__device__ float  g_Hm   [BB*MM*6];        // homography top-2 rows

// ---------------- kernel 1: 8x8 average pool (thread per b,c,y,x) ----------
__global__ void pool_kernel(const float* __restrict__ img) {
    int idx = blockIdx.x * blockDim.x + threadIdx.x;
    if (idx >= BB*CC*HW) return;
    int x = idx % WW;
    int t = idx / WW;
    int y = t % HH;  t /= HH;
    int c = t % CC;
    int b = t / CC;
    const float* base = img + (((size_t)(b*CC + c)*HF + (size_t)y*8)*WF) + (size_t)x*8;
    // 16 independent 16B loads -> deep MLP
    float4 v[16];
#pragma unroll
    for (int r = 0; r < 8; r++) {
        const float4* p = (const float4*)(base + (size_t)r*WF);
        v[2*r]   = p[0];
        v[2*r+1] = p[1];
    }
    float s = 0.f;
#pragma unroll
    for (int k = 0; k < 16; k++) s += v[k].x + v[k].y + v[k].z + v[k].w;
    ((float*)&g_imgp[(size_t)b*HW + (size_t)y*WW + x])[c] = s * (1.f/64.f);
}

// ---------------- kernel 2: depth + normals --------------------------------
__global__ void depth_normal_kernel(const float* __restrict__ disp,
                                    const float* __restrict__ intrs,
                                    const float* __restrict__ baseline) {
    int idx = blockIdx.x * blockDim.x + threadIdx.x;
    if (idx >= BB*HW) return;
    int b = idx / HW, pix = idx % HW, y = pix / WW, x = pix % WW;
    float f  = 0.5f*(intrs[b*9 + 0] + intrs[b*9 + 4]);
    float sc = baseline[b] * f * (1.f/2048.f);
    const float* drow = disp + (size_t)b*HW;
    float dxp = (x < WW-1) ? sc/drow[pix+1]  : 0.f;
    float dxm = (x > 0)    ? sc/drow[pix-1]  : 0.f;
    float dyp = (y < HH-1) ? sc/drow[pix+WW] : 0.f;
    float dym = (y > 0)    ? sc/drow[pix-WW] : 0.f;
    float gx = 0.5f*(dxp - dxm);
    float gy = 0.5f*(dyp - dym);
    float inv = rsqrtf(gx*gx + gy*gy + 1.f);
    g_depth[idx] = sc/drow[pix];
    float* nb = g_nlin + (size_t)b*3*HW;
    nb[pix]          = -gx*inv;
    nb[HW   + pix]   = -gy*inv;
    nb[2*HW + pix]   =  inv;
}

// ---------------- kernel 3: per-plane softmax sums + homography ------------
__global__ void plane_kernel(const float* __restrict__ masks,
                             const float* __restrict__ intrs,
                             const float* __restrict__ baseline) {
    int bm = blockIdx.x;          // 0..BB*MM-1
    int b  = bm / MM;
    int tid = threadIdx.x;        // 256 threads
    const float* mrow = masks + (size_t)bm*HW;

    __shared__ float red[256];
    float mx = -1e30f;
    for (int i = tid; i < HW; i += 256) mx = fmaxf(mx, mrow[i]);
    red[tid] = mx; __syncthreads();
    for (int s = 128; s > 0; s >>= 1) {
        if (tid < s) red[tid] = fmaxf(red[tid], red[tid+s]);
        __syncthreads();
    }
    mx = red[0]; __syncthreads();

    float se=0.f, sd=0.f, s0=0.f, s1=0.f, s2=0.f;
    const float* dep = g_depth + (size_t)b*HW;
    const float* nl  = g_nlin  + (size_t)b*3*HW;
    for (int i = tid; i < HW; i += 256) {
        float e = __expf(mrow[i] - mx);
        se += e;
        sd += e * dep[i];
        int j = 3*i;                      // faithful .view(B, h*w, 3) memory reinterpret
        s0 += e * nl[j];
        s1 += e * nl[j+1];
        s2 += e * nl[j+2];
    }
    __shared__ float r5[5][256];
    r5[0][tid]=se; r5[1][tid]=sd; r5[2][tid]=s0; r5[3][tid]=s1; r5[4][tid]=s2;
    __syncthreads();
    for (int s = 128; s > 0; s >>= 1) {
        if (tid < s)
#pragma unroll
            for (int k = 0; k < 5; k++) r5[k][tid] += r5[k][tid+s];
        __syncthreads();
    }
    if (tid == 0) {
        float inv = 1.f / r5[0][0];
        float d  = r5[1][0]*inv;
        float n0 = r5[2][0]*inv, n1 = r5[3][0]*inv, n2 = r5[4][0]*inv;
        float f  = intrs[b*9+0], g = intrs[b*9+4];
        float cx = intrs[b*9+2], cy = intrs[b*9+5];
        float bl = baseline[b];
        float t0 = bl*n0/d, t1 = bl*n1/d, t2 = bl*n2/d;
        // Hm = K * (I + (bl/d) e3 n^T) * K^-1, top two rows
        float* o = g_Hm + bm*6;
        o[0] = 1.f + cx*t0/f;
        o[1] = cx*t1/g;
        o[2] = cx*t2 - cx*cx*t0/f - cx*cy*t1/g;
        o[3] = cy*t0/f;
        o[4] = 1.f + cy*t1/g;
        o[5] = cy*t2 - cx*cy*t0/f - cy*cy*t1/g;
    }
}

// ---------------- kernel 4: warp + blend -----------------------------------
// One block = 256 consecutive pixels of one batch. Homography -> affine pixel
// coords pre-folded into smem. Two-pass plane softmax (no ev[] register array);
// normalization folded to a single divide at the end.
__global__ __launch_bounds__(256) void warp_blend_kernel(const float* __restrict__ masks,
                                                         float* __restrict__ out) {
    int b   = blockIdx.x / (HW/256);
    int pix = (blockIdx.x % (HW/256))*256 + threadIdx.x;
    int y = pix / WW, x = pix % WW;

    __shared__ float sA[MM][6];   // ix = a*gxx + b*gyy + c ; iy = d*gxx + e*gyy + f
    if (threadIdx.x < MM) {
        const float* Hp = g_Hm + (b*MM + threadIdx.x)*6;
        sA[threadIdx.x][0] = 127.5f*Hp[0];
        sA[threadIdx.x][1] = 127.5f*Hp[1];
        sA[threadIdx.x][2] = 127.5f*(Hp[2] + 1.f);
        sA[threadIdx.x][3] = 63.5f*Hp[3];
        sA[threadIdx.x][4] = 63.5f*Hp[4];
        sA[threadIdx.x][5] = 63.5f*(Hp[5] + 1.f);
    }
    __syncthreads();

    float gxx = -1.f + 2.f*(float)x/(float)(WW-1);
    float gyy = -1.f + 2.f*(float)y/(float)(HH-1);

    const float* mbase = masks + (size_t)b*MM*HW + pix;

    // pass 1: max over planes
    float mx = -1e30f;
#pragma unroll 8
    for (int m = 0; m < MM; m++) mx = fmaxf(mx, mbase[(size_t)m*HW]);

    // pass 2: exp-weighted warp accumulation (normalize at the end)
    const float4* ip = g_imgp + (size_t)b*HW;
    float se = 0.f, a0 = 0.f, a1 = 0.f, a2 = 0.f;
#pragma unroll 4
    for (int m = 0; m < MM; m++) {
        float e = __expf(mbase[(size_t)m*HW] - mx);
        se += e;
        float ix = sA[m][0]*gxx + sA[m][1]*gyy + sA[m][2];
        float iy = sA[m][3]*gxx + sA[m][4]*gyy + sA[m][5];
        float x0f = floorf(ix), y0f = floorf(iy);
        float wx = ix - x0f,    wy = iy - y0f;
        int x0 = (int)x0f, y0 = (int)y0f;
        bool vx0 = (x0   >= 0) && (x0   <= WW-1);
        bool vx1 = (x0+1 >= 0) && (x0+1 <= WW-1);
        bool vy0 = (y0   >= 0) && (y0   <= HH-1);
        bool vy1 = (y0+1 >= 0) && (y0+1 <= HH-1);
        int xc0 = min(max(x0,   0), WW-1), xc1 = min(max(x0+1, 0), WW-1);
        int yc0 = min(max(y0,   0), HH-1), yc1 = min(max(y0+1, 0), HH-1);
        float4 z = make_float4(0.f,0.f,0.f,0.f);
        float4 c00 = (vx0 && vy0) ? ip[yc0*WW + xc0] : z;
        float4 c10 = (vx1 && vy0) ? ip[yc0*WW + xc1] : z;
        float4 c01 = (vx0 && vy1) ? ip[yc1*WW + xc0] : z;
        float4 c11 = (vx1 && vy1) ? ip[yc1*WW + xc1] : z;
        float w00 = (1.f-wx)*(1.f-wy), w10 = wx*(1.f-wy);
        float w01 = (1.f-wx)*wy,       w11 = wx*wy;
        a0 += e*(c00.x*w00 + c10.x*w10 + c01.x*w01 + c11.x*w11);
        a1 += e*(c00.y*w00 + c10.y*w10 + c01.y*w01 + c11.y*w11);
        a2 += e*(c00.z*w00 + c10.z*w10 + c01.z*w01 + c11.z*w11);
    }
    float inv = 1.f/se;
    out[((size_t)b*3 + 0)*HW + pix] = a0*inv;
    out[((size_t)b*3 + 1)*HW + pix] = a1*inv;
    out[((size_t)b*3 + 2)*HW + pix] = a2*inv;
}

// ---------------- launch -----------------------------------------------------
extern "C" void kernel_launch(void* const* d_in, const int* in_sizes, int n_in,
                              void* d_out, int out_size) {
    const float* img      = (const float*)d_in[0];
    const float* masks    = (const float*)d_in[1];
    const float* disp     = (const float*)d_in[2];
    const float* intrs    = (const float*)d_in[3];
    const float* baseline = (const float*)d_in[4];
    float* out = (float*)d_out;

    const int threads = 256;
    const int px_blocks   = (BB*HW + threads - 1) / threads;
    const int pool_blocks = (BB*CC*HW + threads - 1) / threads;

    depth_normal_kernel<<<px_blocks, threads>>>(disp, intrs, baseline);
    plane_kernel<<<BB*MM, threads>>>(masks, intrs, baseline);
    pool_kernel<<<pool_blocks, threads>>>(img);
    warp_blend_kernel<<<px_blocks, threads>>>(masks, out);
}